// round 1
// baseline (speedup 1.0000x reference)
#include <cuda_runtime.h>
#include <math.h>

#define B_ 8
#define C_ 128
#define N_ 2048
#define H_ 4
#define K_ 32
#define D_ 32
#define F_ 512
#define P_ (B_*N_)
#define EPSbn 1e-5f

#define BM 64
#define BN 64
#define BK 16

// ---------------- scratch (static device allocations only) ----------------
__device__ float g_S[B_*N_*N_];        // 128MB scores; reused as FFN hidden h[p][F_]
__device__ int   g_idx[P_*K_];
__device__ float g_xq[P_*C_];
__device__ float g_xk[P_*C_];
__device__ float g_xv[P_*C_];
__device__ float g_x2[P_];
__device__ float g_s1[P_*C_];          // x + o, point-major [p][c]
__device__ float g_x1[P_*C_];
__device__ float g_s2[P_*C_];
__device__ float g_sum1[2*C_];
__device__ float g_sum2[2*C_];
__device__ float g_stat1[2*C_];        // mean, invstd
__device__ float g_stat2[2*C_];

// ---------------- init (must re-run every graph replay) ----------------
__global__ void init_kernel() {
    int t = threadIdx.x;
    if (t < 2*C_) { g_sum1[t] = 0.f; g_sum2[t] = 0.f; }
}

// ---------------- per-point squared norms ----------------
__global__ void colnorm_kernel(const float* __restrict__ x) {
    int p = blockIdx.x*blockDim.x + threadIdx.x;
    if (p >= P_) return;
    int b = p / N_, n = p % N_;
    const float* xb = x + (size_t)b*C_*N_ + n;
    float s = 0.f;
    #pragma unroll
    for (int c = 0; c < C_; c++) { float v = xb[(size_t)c*N_]; s += v*v; }
    g_x2[p] = s;
}

// ---------------- symmetric score GEMM: S[n,m] = dot(x_n,x_m) - 0.5*||x_m||^2 ----
// top-k of S over m == top-k of -dist. Triangular tile enumeration (2x work save).
__global__ __launch_bounds__(256) void score_kernel(const float* __restrict__ x) {
    const int T = N_/BM;   // 32 tiles per dim; pairs = T*(T+1)/2 = 528
    int L = blockIdx.x;
    int i = 0, rem = L;
    while (rem >= T - i) { rem -= (T - i); i++; }
    int j = i + rem;
    int n0 = i*BM, m0 = j*BM;
    int b = blockIdx.z;
    const float* xb  = x + (size_t)b*C_*N_;
    float* Sb        = g_S + (size_t)b*N_*N_;
    const float* x2b = g_x2 + b*N_;

    __shared__ __align__(16) float As[BK][BM+4];
    __shared__ __align__(16) float Bs[BK][BM+4];
    int t = threadIdx.x;
    int tx = t & 15, ty = t >> 4;
    float acc[4][4];
    #pragma unroll
    for (int a = 0; a < 4; a++)
        #pragma unroll
        for (int c = 0; c < 4; c++) acc[a][c] = 0.f;

    for (int k0 = 0; k0 < C_; k0 += BK) {
        #pragma unroll
        for (int q = 0; q < 4; q++) {
            int e = t + q*256;
            int kk = e >> 6, mm = e & 63;
            As[kk][mm] = xb[(size_t)(k0+kk)*N_ + n0 + mm];
            Bs[kk][mm] = xb[(size_t)(k0+kk)*N_ + m0 + mm];
        }
        __syncthreads();
        #pragma unroll
        for (int kk = 0; kk < BK; kk++) {
            float4 av = *(const float4*)&As[kk][ty*4];
            float4 bv = *(const float4*)&Bs[kk][tx*4];
            float a[4] = {av.x, av.y, av.z, av.w};
            float bb[4] = {bv.x, bv.y, bv.z, bv.w};
            #pragma unroll
            for (int aa = 0; aa < 4; aa++)
                #pragma unroll
                for (int cc = 0; cc < 4; cc++) acc[aa][cc] += a[aa]*bb[cc];
        }
        __syncthreads();
    }
    float x2c[4], x2r[4];
    #pragma unroll
    for (int q = 0; q < 4; q++) {
        x2c[q] = x2b[m0 + tx*4 + q];
        x2r[q] = x2b[n0 + ty*4 + q];
    }
    #pragma unroll
    for (int aa = 0; aa < 4; aa++) {
        float4 v;
        v.x = acc[aa][0] - 0.5f*x2c[0];
        v.y = acc[aa][1] - 0.5f*x2c[1];
        v.z = acc[aa][2] - 0.5f*x2c[2];
        v.w = acc[aa][3] - 0.5f*x2c[3];
        *(float4*)&Sb[(size_t)(n0 + ty*4 + aa)*N_ + m0 + tx*4] = v;
    }
    if (i != j) {
        #pragma unroll
        for (int cc = 0; cc < 4; cc++) {
            float4 v;
            v.x = acc[0][cc] - 0.5f*x2r[0];
            v.y = acc[1][cc] - 0.5f*x2r[1];
            v.z = acc[2][cc] - 0.5f*x2r[2];
            v.w = acc[3][cc] - 0.5f*x2r[3];
            *(float4*)&Sb[(size_t)(m0 + tx*4 + cc)*N_ + n0 + ty*4] = v;
        }
    }
}

// ---------------- top-32 per row: value-only iterative argmax over registers ----
__global__ __launch_bounds__(256) void topk_kernel() {
    int row = blockIdx.x;                        // row = b*N_ + n
    const float* Srow = g_S + (size_t)row*N_;
    int t = threadIdx.x;
    float v[8];
    #pragma unroll
    for (int q = 0; q < 8; q++) v[q] = Srow[t + q*256];
    __shared__ float warpmax[8];
    __shared__ int winner;
    int* outp = g_idx + row*K_;
    int lane = t & 31, wid = t >> 5;

    for (int it = 0; it < K_; it++) {
        __syncthreads();                          // all winner reads of prev iter done
        float m = v[0];
        #pragma unroll
        for (int q = 1; q < 8; q++) m = fmaxf(m, v[q]);
        #pragma unroll
        for (int o = 16; o > 0; o >>= 1) m = fmaxf(m, __shfl_xor_sync(0xffffffffu, m, o));
        if (lane == 0) warpmax[wid] = m;
        if (t == 0) winner = 0x7fffffff;
        __syncthreads();
        float bm = warpmax[0];
        #pragma unroll
        for (int q = 1; q < 8; q++) bm = fmaxf(bm, warpmax[q]);
        int li = -1;
        #pragma unroll
        for (int q = 0; q < 8; q++) if (li < 0 && v[q] == bm) li = q;
        unsigned ball = __ballot_sync(0xffffffffu, li >= 0);
        if (li >= 0) {
            int first = __ffs(ball) - 1;
            if (lane == first) atomicMin(&winner, t*8 + li);
        }
        __syncthreads();
        int w = winner;
        if (t == (w >> 3)) {
            int q = w & 7;
            #pragma unroll
            for (int qq = 0; qq < 8; qq++) if (qq == q) v[qq] = -3.0e38f;
        }
        if (t == 0) outp[it] = (w >> 3) + (w & 7)*256;
    }
}

// ---------------- generic strided fp32 GEMM ----------------
// acc(m,n) = sum_k A[k*sAk + m*sAm] * B[k*sBk + n*sBn], C at [m*sCm + n*sCn]
// mode 0: store; mode 2: leaky-relu(0.2); mode 3: +=aux (same layout as C)
__global__ __launch_bounds__(256) void gemm_kernel(
    const float* __restrict__ A, const float* __restrict__ Bm,
    float* __restrict__ Cp, const float* __restrict__ aux,
    int M, int Nd, int Kd,
    long sAk, long sAm, long aOffB,
    long sBk, long sBn, long bOffB,
    long sCm, long sCn, long cOffB,
    int mode)
{
    __shared__ __align__(16) float As[BK][BM+4];
    __shared__ __align__(16) float Bs[BK][BN+4];
    int t = threadIdx.x;
    int tx = t & 15, ty = t >> 4;
    int m0 = blockIdx.y*BM, n0 = blockIdx.x*BN;
    long z = blockIdx.z;
    A  += z*aOffB;
    Bm += z*bOffB;
    Cp += z*cOffB;
    const float* auxp = aux ? (aux + z*cOffB) : nullptr;
    bool aFast = (sAm == 1), bFast = (sBn == 1);
    float acc[4][4];
    #pragma unroll
    for (int a = 0; a < 4; a++)
        #pragma unroll
        for (int c = 0; c < 4; c++) acc[a][c] = 0.f;

    for (int k0 = 0; k0 < Kd; k0 += BK) {
        #pragma unroll
        for (int q = 0; q < 4; q++) {
            int e = t + q*256;
            int kk, mm;
            if (aFast) { kk = e >> 6; mm = e & 63; } else { mm = e >> 4; kk = e & 15; }
            As[kk][mm] = A[(long)(k0+kk)*sAk + (long)(m0+mm)*sAm];
        }
        #pragma unroll
        for (int q = 0; q < 4; q++) {
            int e = t + q*256;
            int kk, nn;
            if (bFast) { kk = e >> 6; nn = e & 63; } else { nn = e >> 4; kk = e & 15; }
            Bs[kk][nn] = Bm[(long)(k0+kk)*sBk + (long)(n0+nn)*sBn];
        }
        __syncthreads();
        #pragma unroll
        for (int kk = 0; kk < BK; kk++) {
            float4 av = *(const float4*)&As[kk][ty*4];
            float4 bv = *(const float4*)&Bs[kk][tx*4];
            float a[4] = {av.x, av.y, av.z, av.w};
            float bb[4] = {bv.x, bv.y, bv.z, bv.w};
            #pragma unroll
            for (int aa = 0; aa < 4; aa++)
                #pragma unroll
                for (int cc = 0; cc < 4; cc++) acc[aa][cc] += a[aa]*bb[cc];
        }
        __syncthreads();
    }
    #pragma unroll
    for (int aa = 0; aa < 4; aa++) {
        int mg = m0 + ty*4 + aa;
        #pragma unroll
        for (int cc = 0; cc < 4; cc++) {
            int ng = n0 + tx*4 + cc;
            float v = acc[aa][cc];
            if (mode == 2) v = v > 0.f ? v : 0.2f*v;
            long off = (long)mg*sCm + (long)ng*sCn;
            if (mode == 3) v += auxp[off];
            Cp[off] = v;
        }
    }
}

// ---------------- attention: one block per point, one warp per head ----------
__global__ __launch_bounds__(128) void attn_kernel(const float* __restrict__ x) {
    int p = blockIdx.x;
    int b = p >> 11, n = p & (N_-1);
    int t = threadIdx.x;
    int h = t >> 5, lane = t & 31;
    __shared__ float qs[C_], ks[C_], vs[C_];
    __shared__ float attns[H_][K_];
    __shared__ int idxs[K_];
    const float scale = 0.17677669529663687f;   // 1/sqrt(D)
    qs[t] = g_xq[(size_t)p*C_ + t] * scale;
    ks[t] = g_xk[(size_t)p*C_ + t];
    vs[t] = g_xv[(size_t)p*C_ + t];
    if (t < K_) idxs[t] = g_idx[p*K_ + t];
    __syncthreads();

    // energy: lane = neighbor index
    int nb = idxs[lane];
    const float* krow = g_xk + ((size_t)(b*N_ + nb))*C_ + h*D_;
    float e = 0.f;
    #pragma unroll
    for (int d = 0; d < D_; d++) e += qs[h*D_ + d] * (krow[d] - ks[h*D_ + d]);
    float mx = e;
    #pragma unroll
    for (int o = 16; o > 0; o >>= 1) mx = fmaxf(mx, __shfl_xor_sync(0xffffffffu, mx, o));
    float ex = __expf(e - mx);
    float sm = ex;
    #pragma unroll
    for (int o = 16; o > 0; o >>= 1) sm += __shfl_xor_sync(0xffffffffu, sm, o);
    attns[h][lane] = ex / sm;
    __syncwarp();

    // output: lane = dim index
    float vself = vs[h*D_ + lane];
    float acc = 0.f;
    #pragma unroll
    for (int jj = 0; jj < K_; jj++) {
        int nbj = idxs[jj];
        float vnb = g_xv[((size_t)(b*N_ + nbj))*C_ + h*D_ + lane];
        acc += attns[h][jj] * (vnb - vself);
    }
    // s1 = x + o   (c == t)
    g_s1[(size_t)p*C_ + t] = x[(size_t)b*C_*N_ + (size_t)t*N_ + n] + acc;
}

// ---------------- BN stats (training-mode, biased var) ----------------
__global__ void bnstats_kernel(int which) {
    const float* src = which ? g_s2 : g_s1;
    float* sums      = which ? g_sum2 : g_sum1;
    int t = threadIdx.x;   // channel
    const float* base = src + (size_t)blockIdx.x*64*C_;
    float s = 0.f, ss = 0.f;
    #pragma unroll 8
    for (int q = 0; q < 64; q++) { float v = base[(size_t)q*C_ + t]; s += v; ss += v*v; }
    atomicAdd(&sums[t], s);
    atomicAdd(&sums[t + C_], ss);
}

__global__ void bnfin_kernel(int which) {
    const float* sums = which ? g_sum2 : g_sum1;
    float* stat       = which ? g_stat2 : g_stat1;
    int c = threadIdx.x;
    float m = sums[c] * (1.f/(float)P_);
    float var = sums[c + C_] * (1.f/(float)P_) - m*m;
    stat[c] = m;
    stat[c + C_] = rsqrtf(var + EPSbn);
}

__global__ void x1_kernel(const float* __restrict__ g1, const float* __restrict__ b1) {
    int i = blockIdx.x*blockDim.x + threadIdx.x;
    if (i >= P_*C_) return;
    int c = i & (C_-1);
    g_x1[i] = (g_s1[i] - g_stat1[c]) * g_stat1[c + C_] * g1[c] + b1[c];
}

// ---------------- final BN2 + transpose to [B,C,N] ----------------
__global__ void out_kernel(float* __restrict__ out,
                           const float* __restrict__ g2, const float* __restrict__ b2) {
    __shared__ float tile[32][33];
    int b = blockIdx.z;
    int n0 = blockIdx.x*32, c0 = blockIdx.y*32;
    int tx = threadIdx.x, ty = threadIdx.y;   // 32 x 8
    #pragma unroll
    for (int r = 0; r < 4; r++) {
        int nl = ty + r*8;
        int c = c0 + tx;
        float v = g_s2[(size_t)(b*N_ + n0 + nl)*C_ + c];
        v = (v - g_stat2[c]) * g_stat2[c + C_] * g2[c] + b2[c];
        tile[nl][tx] = v;
    }
    __syncthreads();
    #pragma unroll
    for (int r = 0; r < 4; r++) {
        int cl = ty + r*8;
        out[(size_t)b*C_*N_ + (size_t)(c0 + cl)*N_ + n0 + tx] = tile[tx][cl];
    }
}

// ---------------- launch ----------------
extern "C" void kernel_launch(void* const* d_in, const int* in_sizes, int n_in,
                              void* d_out, int out_size) {
    const float* x  = (const float*)d_in[0];
    const float* wq = (const float*)d_in[1];
    const float* wk = (const float*)d_in[2];
    const float* wv = (const float*)d_in[3];
    const float* w1 = (const float*)d_in[4];
    const float* w2 = (const float*)d_in[5];
    const float* g1 = (const float*)d_in[6];
    const float* b1 = (const float*)d_in[7];
    const float* g2 = (const float*)d_in[8];
    const float* b2 = (const float*)d_in[9];
    float* out = (float*)d_out;

    void *pS, *pxq, *pxk, *pxv, *px1, *ps2;
    cudaGetSymbolAddress(&pS,  g_S);
    cudaGetSymbolAddress(&pxq, g_xq);
    cudaGetSymbolAddress(&pxk, g_xk);
    cudaGetSymbolAddress(&pxv, g_xv);
    cudaGetSymbolAddress(&px1, g_x1);
    cudaGetSymbolAddress(&ps2, g_s2);

    init_kernel<<<1, 256>>>();
    colnorm_kernel<<<P_/256, 256>>>(x);
    score_kernel<<<dim3(528, 1, B_), 256>>>(x);
    topk_kernel<<<P_, 256>>>();

    // q, k, v projections: acc(n_pt, o) = sum_c x[b,c,n] * w[o,c], stored [p][c]
    gemm_kernel<<<dim3(C_/BN, N_/BM, B_), 256>>>(x, wq, (float*)pxq, nullptr,
        N_, C_, C_,
        (long)N_, 1L, (long)C_*N_,
        1L, (long)C_, 0L,
        (long)C_, 1L, (long)N_*C_, 0);
    gemm_kernel<<<dim3(C_/BN, N_/BM, B_), 256>>>(x, wk, (float*)pxk, nullptr,
        N_, C_, C_,
        (long)N_, 1L, (long)C_*N_,
        1L, (long)C_, 0L,
        (long)C_, 1L, (long)N_*C_, 0);
    gemm_kernel<<<dim3(C_/BN, N_/BM, B_), 256>>>(x, wv, (float*)pxv, nullptr,
        N_, C_, C_,
        (long)N_, 1L, (long)C_*N_,
        1L, (long)C_, 0L,
        (long)C_, 1L, (long)N_*C_, 0);

    attn_kernel<<<P_, 128>>>(x);

    bnstats_kernel<<<P_/64, 128>>>(0);
    bnfin_kernel<<<1, 128>>>(0);
    x1_kernel<<<(P_*C_)/256, 256>>>(g1, b1);

    // h = leaky(w1 @ x1), h stored [p][F_] in g_S scratch
    gemm_kernel<<<dim3(P_/BN, F_/BM, 1), 256>>>(w1, (float*)px1, (float*)pS, nullptr,
        F_, P_, C_,
        1L, (long)C_, 0L,
        1L, (long)C_, 0L,
        1L, (long)F_, 0L, 2);
    // s2 = x1 + w2 @ h
    gemm_kernel<<<dim3(P_/BN, C_/BM, 1), 256>>>(w2, (float*)pS, (float*)ps2, (float*)px1,
        C_, P_, F_,
        1L, (long)F_, 0L,
        1L, (long)F_, 0L,
        1L, (long)C_, 0L, 3);

    bnstats_kernel<<<P_/64, 128>>>(1);
    bnfin_kernel<<<1, 128>>>(1);

    out_kernel<<<dim3(N_/32, C_/32, B_), dim3(32, 8)>>>(out, g2, b2);
}

// round 2
// speedup vs baseline: 1.4301x; 1.4301x over previous
#include <cuda_runtime.h>
#include <math.h>

#define B_ 8
#define C_ 128
#define N_ 2048
#define H_ 4
#define K_ 32
#define D_ 32
#define F_ 512
#define P_ (B_*N_)
#define EPSbn 1e-5f

#define BM 64
#define BN 64
#define BK 16

// ---------------- scratch (static device allocations only) ----------------
__device__ float g_S[B_*N_*N_];        // 128MB scores; reused as FFN hidden h[p][F_]
__device__ int   g_idx[P_*K_];
__device__ float g_xq[P_*C_];
__device__ float g_xk[P_*C_];
__device__ float g_xv[P_*C_];
__device__ float g_x2[P_];
__device__ float g_s1[P_*C_];          // x + o, point-major [p][c]
__device__ float g_x1[P_*C_];
__device__ float g_s2[P_*C_];
__device__ float g_sum1[2*C_];
__device__ float g_sum2[2*C_];
__device__ float g_stat1[2*C_];        // mean, invstd
__device__ float g_stat2[2*C_];

// ---------------- init (must re-run every graph replay) ----------------
__global__ void init_kernel() {
    int t = threadIdx.x;
    if (t < 2*C_) { g_sum1[t] = 0.f; g_sum2[t] = 0.f; }
}

// ---------------- per-point squared norms ----------------
__global__ void colnorm_kernel(const float* __restrict__ x) {
    int p = blockIdx.x*blockDim.x + threadIdx.x;
    if (p >= P_) return;
    int b = p / N_, n = p % N_;
    const float* xb = x + (size_t)b*C_*N_ + n;
    float s = 0.f;
    #pragma unroll
    for (int c = 0; c < C_; c++) { float v = xb[(size_t)c*N_]; s += v*v; }
    g_x2[p] = s;
}

// ---------------- symmetric score GEMM: S[n,m] = dot(x_n,x_m) - 0.5*||x_m||^2 ----
__global__ __launch_bounds__(256) void score_kernel(const float* __restrict__ x) {
    const int T = N_/BM;   // 32 tiles per dim; pairs = 528
    int L = blockIdx.x;
    int i = 0, rem = L;
    while (rem >= T - i) { rem -= (T - i); i++; }
    int j = i + rem;
    int n0 = i*BM, m0 = j*BM;
    int b = blockIdx.z;
    const float* xb  = x + (size_t)b*C_*N_;
    float* Sb        = g_S + (size_t)b*N_*N_;
    const float* x2b = g_x2 + b*N_;

    __shared__ __align__(16) float As[BK][BM+4];
    __shared__ __align__(16) float Bs[BK][BM+4];
    int t = threadIdx.x;
    int tx = t & 15, ty = t >> 4;
    float acc[4][4];
    #pragma unroll
    for (int a = 0; a < 4; a++)
        #pragma unroll
        for (int c = 0; c < 4; c++) acc[a][c] = 0.f;

    for (int k0 = 0; k0 < C_; k0 += BK) {
        #pragma unroll
        for (int q = 0; q < 4; q++) {
            int e = t + q*256;
            int kk = e >> 6, mm = e & 63;
            As[kk][mm] = xb[(size_t)(k0+kk)*N_ + n0 + mm];
            Bs[kk][mm] = xb[(size_t)(k0+kk)*N_ + m0 + mm];
        }
        __syncthreads();
        #pragma unroll
        for (int kk = 0; kk < BK; kk++) {
            float4 av = *(const float4*)&As[kk][ty*4];
            float4 bv = *(const float4*)&Bs[kk][tx*4];
            float a[4] = {av.x, av.y, av.z, av.w};
            float bb[4] = {bv.x, bv.y, bv.z, bv.w};
            #pragma unroll
            for (int aa = 0; aa < 4; aa++)
                #pragma unroll
                for (int cc = 0; cc < 4; cc++) acc[aa][cc] += a[aa]*bb[cc];
        }
        __syncthreads();
    }
    float x2c[4], x2r[4];
    #pragma unroll
    for (int q = 0; q < 4; q++) {
        x2c[q] = x2b[m0 + tx*4 + q];
        x2r[q] = x2b[n0 + ty*4 + q];
    }
    #pragma unroll
    for (int aa = 0; aa < 4; aa++) {
        float4 v;
        v.x = acc[aa][0] - 0.5f*x2c[0];
        v.y = acc[aa][1] - 0.5f*x2c[1];
        v.z = acc[aa][2] - 0.5f*x2c[2];
        v.w = acc[aa][3] - 0.5f*x2c[3];
        *(float4*)&Sb[(size_t)(n0 + ty*4 + aa)*N_ + m0 + tx*4] = v;
    }
    if (i != j) {
        #pragma unroll
        for (int cc = 0; cc < 4; cc++) {
            float4 v;
            v.x = acc[0][cc] - 0.5f*x2r[0];
            v.y = acc[1][cc] - 0.5f*x2r[1];
            v.z = acc[2][cc] - 0.5f*x2r[2];
            v.w = acc[3][cc] - 0.5f*x2r[3];
            *(float4*)&Sb[(size_t)(m0 + tx*4 + cc)*N_ + n0 + ty*4] = v;
        }
    }
}

// ---------------- top-32 per row: exact 4-pass radix select (8-bit digits) ----
// Output set identical to sorted top-k (ties -> smallest indices). Order of
// emitted indices is irrelevant: downstream softmax+sum is permutation-invariant.
__global__ __launch_bounds__(256) void topk_kernel() {
    int row = blockIdx.x;
    const float* Srow = g_S + (size_t)row*N_;
    int t = threadIdx.x;
    unsigned u[8];
    #pragma unroll
    for (int q = 0; q < 8; q++) {
        unsigned b = __float_as_uint(Srow[t + q*256]);
        u[q] = (b & 0x80000000u) ? ~b : (b | 0x80000000u);   // monotone map
    }
    __shared__ unsigned hist[256];
    __shared__ unsigned suffix[256];
    __shared__ unsigned wsum[8];
    __shared__ unsigned sh_prefix;
    __shared__ int sh_need, sh_cnt, sh_eqcnt;
    __shared__ int eqbuf[256];
    if (t == 0) { sh_prefix = 0u; sh_need = K_; }
    int lane = t & 31, wid = t >> 5;

    #pragma unroll
    for (int pass = 0; pass < 4; pass++) {
        int shift = 24 - pass*8;
        hist[t] = 0u;
        __syncthreads();                       // prev writer + hist zero visible
        unsigned pref = sh_prefix;
        int need = sh_need;
        unsigned mask = (pass == 0) ? 0u : (0xFFFFFFFFu << (shift + 8));
        #pragma unroll
        for (int q = 0; q < 8; q++)
            if ((u[q] & mask) == pref)
                atomicAdd(&hist[(u[q] >> shift) & 255u], 1u);
        __syncthreads();
        // suffix[b] = sum_{i>=b} hist[i]  (scan over reversed bin order)
        int r = 255 - t;
        unsigned val = hist[r];
        #pragma unroll
        for (int o = 1; o < 32; o <<= 1) {
            unsigned up = __shfl_up_sync(0xffffffffu, val, o);
            if (lane >= o) val += up;
        }
        if (lane == 31) wsum[wid] = val;
        __syncthreads();
        #pragma unroll
        for (int w = 0; w < 8; w++) if (w < wid) val += wsum[w];
        suffix[r] = val;
        __syncthreads();
        unsigned nxt = (r == 255) ? 0u : suffix[r + 1];
        if (suffix[r] >= (unsigned)need && nxt < (unsigned)need) {
            sh_prefix = pref | ((unsigned)r << shift);
            sh_need = need - (int)nxt;
        }
        __syncthreads();
    }

    unsigned T = sh_prefix;       // exact 32nd-largest value (monotone space)
    int need_eq = sh_need;        // how many == T to keep (smallest indices)
    if (t == 0) { sh_cnt = 0; sh_eqcnt = 0; }
    __syncthreads();
    int* outp = g_idx + row*K_;
    #pragma unroll
    for (int q = 0; q < 8; q++) {
        if (u[q] > T) {
            int pos = atomicAdd(&sh_cnt, 1);
            outp[pos] = t + q*256;
        } else if (u[q] == T) {
            int e = atomicAdd(&sh_eqcnt, 1);
            if (e < 256) eqbuf[e] = t + q*256;
        }
    }
    __syncthreads();
    if (t == 0) {
        int cnt = sh_cnt;
        int m = sh_eqcnt; if (m > 256) m = 256;
        for (int i = 0; i < need_eq; i++) {
            int best = 0x7fffffff, bj = -1;
            for (int j = 0; j < m; j++)
                if (eqbuf[j] < best) { best = eqbuf[j]; bj = j; }
            eqbuf[bj] = 0x7fffffff;
            outp[cnt + i] = best;
        }
    }
}

// ---------------- generic strided fp32 GEMM ----------------
__global__ __launch_bounds__(256) void gemm_kernel(
    const float* __restrict__ A, const float* __restrict__ Bm,
    float* __restrict__ Cp, const float* __restrict__ aux,
    int M, int Nd, int Kd,
    long sAk, long sAm, long aOffB,
    long sBk, long sBn, long bOffB,
    long sCm, long sCn, long cOffB,
    int mode)
{
    __shared__ __align__(16) float As[BK][BM+4];
    __shared__ __align__(16) float Bs[BK][BN+4];
    int t = threadIdx.x;
    int tx = t & 15, ty = t >> 4;
    int m0 = blockIdx.y*BM, n0 = blockIdx.x*BN;
    long z = blockIdx.z;
    A  += z*aOffB;
    Bm += z*bOffB;
    Cp += z*cOffB;
    const float* auxp = aux ? (aux + z*cOffB) : nullptr;
    bool aFast = (sAm == 1), bFast = (sBn == 1);
    float acc[4][4];
    #pragma unroll
    for (int a = 0; a < 4; a++)
        #pragma unroll
        for (int c = 0; c < 4; c++) acc[a][c] = 0.f;

    for (int k0 = 0; k0 < Kd; k0 += BK) {
        #pragma unroll
        for (int q = 0; q < 4; q++) {
            int e = t + q*256;
            int kk, mm;
            if (aFast) { kk = e >> 6; mm = e & 63; } else { mm = e >> 4; kk = e & 15; }
            As[kk][mm] = A[(long)(k0+kk)*sAk + (long)(m0+mm)*sAm];
        }
        #pragma unroll
        for (int q = 0; q < 4; q++) {
            int e = t + q*256;
            int kk, nn;
            if (bFast) { kk = e >> 6; nn = e & 63; } else { nn = e >> 4; kk = e & 15; }
            Bs[kk][nn] = Bm[(long)(k0+kk)*sBk + (long)(n0+nn)*sBn];
        }
        __syncthreads();
        #pragma unroll
        for (int kk = 0; kk < BK; kk++) {
            float4 av = *(const float4*)&As[kk][ty*4];
            float4 bv = *(const float4*)&Bs[kk][tx*4];
            float a[4] = {av.x, av.y, av.z, av.w};
            float bb[4] = {bv.x, bv.y, bv.z, bv.w};
            #pragma unroll
            for (int aa = 0; aa < 4; aa++)
                #pragma unroll
                for (int cc = 0; cc < 4; cc++) acc[aa][cc] += a[aa]*bb[cc];
        }
        __syncthreads();
    }
    #pragma unroll
    for (int aa = 0; aa < 4; aa++) {
        int mg = m0 + ty*4 + aa;
        #pragma unroll
        for (int cc = 0; cc < 4; cc++) {
            int ng = n0 + tx*4 + cc;
            float v = acc[aa][cc];
            if (mode == 2) v = v > 0.f ? v : 0.2f*v;
            long off = (long)mg*sCm + (long)ng*sCn;
            if (mode == 3) v += auxp[off];
            Cp[off] = v;
        }
    }
}

// ---------------- attention: one block per point, one warp per head ----------
__global__ __launch_bounds__(128) void attn_kernel(const float* __restrict__ x) {
    int p = blockIdx.x;
    int b = p >> 11, n = p & (N_-1);
    int t = threadIdx.x;
    int h = t >> 5, lane = t & 31;
    __shared__ float qs[C_], ks[C_], vs[C_];
    __shared__ float attns[H_][K_];
    __shared__ int idxs[K_];
    const float scale = 0.17677669529663687f;   // 1/sqrt(D)
    qs[t] = g_xq[(size_t)p*C_ + t] * scale;
    ks[t] = g_xk[(size_t)p*C_ + t];
    vs[t] = g_xv[(size_t)p*C_ + t];
    if (t < K_) idxs[t] = g_idx[p*K_ + t];
    __syncthreads();

    int nb = idxs[lane];
    const float* krow = g_xk + ((size_t)(b*N_ + nb))*C_ + h*D_;
    float e = 0.f;
    #pragma unroll
    for (int d = 0; d < D_; d++) e += qs[h*D_ + d] * (krow[d] - ks[h*D_ + d]);
    float mx = e;
    #pragma unroll
    for (int o = 16; o > 0; o >>= 1) mx = fmaxf(mx, __shfl_xor_sync(0xffffffffu, mx, o));
    float ex = __expf(e - mx);
    float sm = ex;
    #pragma unroll
    for (int o = 16; o > 0; o >>= 1) sm += __shfl_xor_sync(0xffffffffu, sm, o);
    attns[h][lane] = ex / sm;
    __syncwarp();

    float vself = vs[h*D_ + lane];
    float acc = 0.f;
    #pragma unroll
    for (int jj = 0; jj < K_; jj++) {
        int nbj = idxs[jj];
        float vnb = g_xv[((size_t)(b*N_ + nbj))*C_ + h*D_ + lane];
        acc += attns[h][jj] * (vnb - vself);
    }
    g_s1[(size_t)p*C_ + t] = x[(size_t)b*C_*N_ + (size_t)t*N_ + n] + acc;
}

// ---------------- BN stats (training-mode, biased var) ----------------
__global__ void bnstats_kernel(int which) {
    const float* src = which ? g_s2 : g_s1;
    float* sums      = which ? g_sum2 : g_sum1;
    int t = threadIdx.x;   // channel
    const float* base = src + (size_t)blockIdx.x*64*C_;
    float s = 0.f, ss = 0.f;
    #pragma unroll 8
    for (int q = 0; q < 64; q++) { float v = base[(size_t)q*C_ + t]; s += v; ss += v*v; }
    atomicAdd(&sums[t], s);
    atomicAdd(&sums[t + C_], ss);
}

__global__ void bnfin_kernel(int which) {
    const float* sums = which ? g_sum2 : g_sum1;
    float* stat       = which ? g_stat2 : g_stat1;
    int c = threadIdx.x;
    float m = sums[c] * (1.f/(float)P_);
    float var = sums[c + C_] * (1.f/(float)P_) - m*m;
    stat[c] = m;
    stat[c + C_] = rsqrtf(var + EPSbn);
}

__global__ void x1_kernel(const float* __restrict__ g1, const float* __restrict__ b1) {
    int i = blockIdx.x*blockDim.x + threadIdx.x;
    if (i >= P_*C_) return;
    int c = i & (C_-1);
    g_x1[i] = (g_s1[i] - g_stat1[c]) * g_stat1[c + C_] * g1[c] + b1[c];
}

// ---------------- final BN2 + transpose to [B,C,N] ----------------
__global__ void out_kernel(float* __restrict__ out,
                           const float* __restrict__ g2, const float* __restrict__ b2) {
    __shared__ float tile[32][33];
    int b = blockIdx.z;
    int n0 = blockIdx.x*32, c0 = blockIdx.y*32;
    int tx = threadIdx.x, ty = threadIdx.y;   // 32 x 8
    #pragma unroll
    for (int r = 0; r < 4; r++) {
        int nl = ty + r*8;
        int c = c0 + tx;
        float v = g_s2[(size_t)(b*N_ + n0 + nl)*C_ + c];
        v = (v - g_stat2[c]) * g_stat2[c + C_] * g2[c] + b2[c];
        tile[nl][tx] = v;
    }
    __syncthreads();
    #pragma unroll
    for (int r = 0; r < 4; r++) {
        int cl = ty + r*8;
        out[(size_t)b*C_*N_ + (size_t)(c0 + cl)*N_ + n0 + tx] = tile[tx][cl];
    }
}

// ---------------- launch ----------------
extern "C" void kernel_launch(void* const* d_in, const int* in_sizes, int n_in,
                              void* d_out, int out_size) {
    const float* x  = (const float*)d_in[0];
    const float* wq = (const float*)d_in[1];
    const float* wk = (const float*)d_in[2];
    const float* wv = (const float*)d_in[3];
    const float* w1 = (const float*)d_in[4];
    const float* w2 = (const float*)d_in[5];
    const float* g1 = (const float*)d_in[6];
    const float* b1 = (const float*)d_in[7];
    const float* g2 = (const float*)d_in[8];
    const float* b2 = (const float*)d_in[9];
    float* out = (float*)d_out;

    void *pS, *pxq, *pxk, *pxv, *px1, *ps2;
    cudaGetSymbolAddress(&pS,  g_S);
    cudaGetSymbolAddress(&pxq, g_xq);
    cudaGetSymbolAddress(&pxk, g_xk);
    cudaGetSymbolAddress(&pxv, g_xv);
    cudaGetSymbolAddress(&px1, g_x1);
    cudaGetSymbolAddress(&ps2, g_s2);

    init_kernel<<<1, 256>>>();
    colnorm_kernel<<<P_/256, 256>>>(x);
    score_kernel<<<dim3(528, 1, B_), 256>>>(x);
    topk_kernel<<<P_, 256>>>();

    gemm_kernel<<<dim3(C_/BN, N_/BM, B_), 256>>>(x, wq, (float*)pxq, nullptr,
        N_, C_, C_,
        (long)N_, 1L, (long)C_*N_,
        1L, (long)C_, 0L,
        (long)C_, 1L, (long)N_*C_, 0);
    gemm_kernel<<<dim3(C_/BN, N_/BM, B_), 256>>>(x, wk, (float*)pxk, nullptr,
        N_, C_, C_,
        (long)N_, 1L, (long)C_*N_,
        1L, (long)C_, 0L,
        (long)C_, 1L, (long)N_*C_, 0);
    gemm_kernel<<<dim3(C_/BN, N_/BM, B_), 256>>>(x, wv, (float*)pxv, nullptr,
        N_, C_, C_,
        (long)N_, 1L, (long)C_*N_,
        1L, (long)C_, 0L,
        (long)C_, 1L, (long)N_*C_, 0);

    attn_kernel<<<P_, 128>>>(x);

    bnstats_kernel<<<P_/64, 128>>>(0);
    bnfin_kernel<<<1, 128>>>(0);
    x1_kernel<<<(P_*C_)/256, 256>>>(g1, b1);

    gemm_kernel<<<dim3(P_/BN, F_/BM, 1), 256>>>(w1, (float*)px1, (float*)pS, nullptr,
        F_, P_, C_,
        1L, (long)C_, 0L,
        1L, (long)C_, 0L,
        1L, (long)F_, 0L, 2);
    gemm_kernel<<<dim3(P_/BN, C_/BM, 1), 256>>>(w2, (float*)pS, (float*)ps2, (float*)px1,
        C_, P_, F_,
        1L, (long)F_, 0L,
        1L, (long)F_, 0L,
        1L, (long)C_, 0L, 3);

    bnstats_kernel<<<P_/64, 128>>>(1);
    bnfin_kernel<<<1, 128>>>(1);

    out_kernel<<<dim3(N_/32, C_/32, B_), dim3(32, 8)>>>(out, g2, b2);
}